// round 11
// baseline (speedup 1.0000x reference)
#include <cuda_runtime.h>
#include <cuda_bf16.h>
#include <math.h>
#include <cstdint>

#define MAXN 200000
#define MAXB 2
#define IMG_H 300
#define IMG_W 400
#define HW (IMG_H * IMG_W)
#define DFEAT 256
#define HID 256

// ---------------- scratch (static device globals; no allocation) ----------------
__device__ float g_vdir[(size_t)MAXB * MAXN * 3];
__device__ float g_wts[(size_t)MAXB * MAXN];
__device__ int   g_idx[(size_t)MAXB * MAXN];
__device__ float g_num[(size_t)MAXB * HW * 3];
__device__ float g_den[(size_t)MAXB * HW];
__device__ float g_pinv[MAXB * 16];
__device__ __nv_bfloat16 g_W1T[DFEAT * HID];   // W1T[n][k] = W1[k][n], bf16, K-major
__device__ float g_pa[2][(size_t)MAXB * MAXN * 3];  // partial pre-sigmoid sums per half

__device__ __forceinline__ float sigmoidf_(float x) {
    return 1.0f / (1.0f + expf(-x));
}

// No-FMA dot product — matches XLA fusion codegen. DO NOT TOUCH.
__device__ __forceinline__ float dot3_nofma(float a0, float a1, float a2,
                                            float x0, float x1, float x2) {
    float t0 = __fmul_rn(a0, x0);
    float t1 = __fmul_rn(a1, x1);
    float t2 = __fmul_rn(a2, x2);
    return __fadd_rn(__fadd_rn(t0, t1), t2);
}

__device__ __forceinline__ uint32_t smem_to_u32(const void* p) {
    uint32_t a;
    asm("{ .reg .u64 t; cvta.to.shared.u64 t, %1; cvt.u32.u64 %0, t; }" : "=r"(a) : "l"(p));
    return a;
}

// ---------------- 1) 4x4 pose inverse ----------------
__global__ void prep_kernel(const float* __restrict__ pose, int B) {
    int b = threadIdx.x;
    if (b >= B) return;
    float a[4][8];
    for (int r = 0; r < 4; r++)
        for (int c = 0; c < 4; c++) {
            a[r][c] = pose[b * 16 + r * 4 + c];
            a[r][4 + c] = (r == c) ? 1.0f : 0.0f;
        }
    for (int col = 0; col < 4; col++) {
        int piv = col;
        for (int r = col + 1; r < 4; r++)
            if (fabsf(a[r][col]) > fabsf(a[piv][col])) piv = r;
        if (piv != col)
            for (int c = 0; c < 8; c++) { float t = a[col][c]; a[col][c] = a[piv][c]; a[piv][c] = t; }
        float d = 1.0f / a[col][col];
        for (int c = 0; c < 8; c++) a[col][c] *= d;
        for (int r = 0; r < 4; r++) {
            if (r == col) continue;
            float f = a[r][col];
            for (int c = 0; c < 8; c++) a[r][c] -= f * a[col][c];
        }
    }
    for (int r = 0; r < 4; r++)
        for (int c = 0; c < 4; c++)
            g_pinv[b * 16 + r * 4 + c] = a[r][4 + c];
}

// ------- 2) init: zero accumulators + convert W1[0:256] -> bf16 K-major -------
__global__ void init_kernel(const float* __restrict__ W1, int B) {
    int i = blockIdx.x * blockDim.x + threadIdx.x;
    if (i < DFEAT * HID) {
        int k = i >> 8, n = i & 255;            // read coalesced over n
        g_W1T[n * DFEAT + k] = __float2bfloat16(W1[k * HID + n]);
    }
    int n3 = B * HW * 3;
    if (i < n3) g_num[i] = 0.0f;
    if (i < B * HW) g_den[i] = 0.0f;
}

// ---------------- 3) geometry (exact arithmetic — passes at 9e-8) ----------------
__global__ void geom_kernel(const float* __restrict__ vert_pos,
                            const float* __restrict__ pose,
                            const float* __restrict__ intr,
                            const float* __restrict__ opy,
                            int N, int B) {
    int i = blockIdx.x * blockDim.x + threadIdx.x;
    if (i >= B * N) return;
    int b = i / N, n = i - b * N;

    float px = vert_pos[n], py = vert_pos[N + n], pz = vert_pos[2 * N + n];
    const float* P = pose + b * 16;
    float x = __fadd_rn(dot3_nofma(P[0], P[1], P[2],  px, py, pz), __fmul_rn(P[3],  1.0f));
    float y = __fadd_rn(dot3_nofma(P[4], P[5], P[6],  px, py, pz), __fmul_rn(P[7],  1.0f));
    float z = __fadd_rn(dot3_nofma(P[8], P[9], P[10], px, py, pz), __fmul_rn(P[11], 1.0f));

    const float* Km = intr + b * 9;
    float u_ = dot3_nofma(Km[0], Km[1], Km[2], x, y, z);
    float v_ = dot3_nofma(Km[3], Km[4], Km[5], x, y, z);
    float w_ = dot3_nofma(Km[6], Km[7], Km[8], x, y, z);

    bool em = fabsf(w_) < 0.01f;
    float zs = em ? 0.01f : w_;
    float su = em ? -1e6f : __fdiv_rn(u_, zs);
    float sv = em ? -1e6f : __fdiv_rn(v_, zs);
    float sz = em ? -1e6f : zs;

    float inorm = rsqrtf(x * x + y * y + z * z);
    float nx = x * inorm, ny = y * inorm, nz = z * inorm;
    const float* Pi = g_pinv + b * 16;
    g_vdir[(size_t)i * 3 + 0] = dot3_nofma(Pi[0], Pi[1], Pi[2],  nx, ny, nz);
    g_vdir[(size_t)i * 3 + 1] = dot3_nofma(Pi[4], Pi[5], Pi[6],  nx, ny, nz);
    g_vdir[(size_t)i * 3 + 2] = dot3_nofma(Pi[8], Pi[9], Pi[10], nx, ny, nz);

    int ix = (int)rintf(su);
    int iy = (int)rintf(sv);
    bool valid = (ix >= 0) && (ix < IMG_W) && (iy >= 0) && (iy < IMG_H) && (sz >= 1.0f);
    g_idx[i] = valid ? iy * IMG_W + ix : HW;
    float op = sigmoidf_(opy[n]);
    op = fminf(fmaxf(op, 0.0f), 1.0f);
    g_wts[i] = valid ? op : 0.0f;
}

// ====== 4) split-N fused GEMM: 2 CTAs/SM, each CTA = (rowtile, half-of-hidden) ======
// CTA: 64 points x 128 hidden cols x K=256, 256 threads (8 warps, 2m x 4n grid,
// warp tile 32x32 — same per-warp code as the validated round-10 kernel).
// Writes partial pre-sigmoid sums to g_pa[half] (plain stores, one owner each).
#define TILE_ROWS 64
#define GRID_F 304
// per-CTA SMEM offsets
#define SMB   0                      // B half-tile: 128 n-rows x 512B     = 65536
#define SMA   65536                  // A tile: 64 rows x 512B             = 32768
#define SMT1  98304                  // t1[256] float4 {b1,w0,w1,w2}       = 4096
#define SMT2  102400                 // t2[256] float4 {Wa,Wb,Wc,-}        = 4096
#define SMVD  106496                 // vdir  [2][64][3] floats            = 1536
#define SMRA  108032                 // rowacc[2][64][3] floats            = 1536
#define SM_TOTAL 109568              // x2 CTAs = 219136 <= 228KB/SM

__device__ __forceinline__ void ldmatrix_x4(uint32_t* r, uint32_t addr) {
    asm volatile("ldmatrix.sync.aligned.m8n8.x4.shared.b16 {%0,%1,%2,%3}, [%4];"
                 : "=r"(r[0]), "=r"(r[1]), "=r"(r[2]), "=r"(r[3]) : "r"(addr));
}
__device__ __forceinline__ void mma_bf16(float* d, const uint32_t* a, const uint32_t* b) {
    asm volatile(
        "mma.sync.aligned.m16n8k16.row.col.f32.bf16.bf16.f32 "
        "{%0,%1,%2,%3}, {%4,%5,%6,%7}, {%8,%9}, {%0,%1,%2,%3};"
        : "+f"(d[0]), "+f"(d[1]), "+f"(d[2]), "+f"(d[3])
        : "r"(a[0]), "r"(a[1]), "r"(a[2]), "r"(a[3]), "r"(b[0]), "r"(b[1]));
}

__global__ __launch_bounds__(256, 2) void fused_gemm_kernel(
    const float* __restrict__ feat,
    const float* __restrict__ W1,
    const float* __restrict__ b1g,
    const float* __restrict__ W2g,
    int Npts, int B, int nunits)
{
    extern __shared__ char smem[];
    uint32_t smem_u = smem_to_u32(smem);
    int tid = threadIdx.x;
    int wid = tid >> 5;                // 0..7
    int lane = tid & 31;
    int g = lane >> 2;
    int tig = lane & 3;
    int half = blockIdx.x & 1;         // fixed per CTA (grid stride 304 is even)

    float4* s_t1 = (float4*)(smem + SMT1);
    float4* s_t2 = (float4*)(smem + SMT2);
    float* s_vd  = (float*)(smem + SMVD);    // [(b*64+r)*3 + c]
    float* s_ra  = (float*)(smem + SMRA);    // [(b*64+r)*3 + c]

    // ---- load B half-tile ONCE: rows n = half*128 + n_local, 128 x 256 bf16 ----
    for (int i = 0; i < 16; i++) {
        int it = tid + i * 256;              // 0..4095 uint4
        int nl = it >> 5;                    // local n row 0..127
        int chunk = it & 31;
        int n = half * 128 + nl;
        uint4 v = *(const uint4*)(g_W1T + (size_t)n * DFEAT + (chunk << 3));
        uint32_t off = (uint32_t)nl * 512 + (uint32_t)((chunk ^ (nl & 7)) << 4);
        *(uint4*)(smem + SMB + off) = v;
    }
    // ---- full tables (both halves; indexed by global j) ----
    if (tid < 256) {
        s_t1[tid] = make_float4(b1g[tid],
                                W1[(size_t)DFEAT * HID + tid],
                                W1[(size_t)(DFEAT + 1) * HID + tid],
                                W1[(size_t)(DFEAT + 2) * HID + tid]);
        s_t2[tid] = make_float4(W2g[tid * 3 + 0], W2g[tid * 3 + 1],
                                W2g[tid * 3 + 2], 0.0f);
    }
    if (tid < 128) {                         // zero all 384 rowacc floats
        s_ra[tid] = 0.0f; s_ra[128 + tid] = 0.0f; s_ra[256 + tid] = 0.0f;
    }

    // ---- warp tiling / ldmatrix addressing (identical per-warp to round 10) ----
    int warpRow = (wid >> 2) * 32;           // 0 or 32
    int warpColL = (wid & 3) * 32;           // local col 0..96
    int a_roff = (lane < 16) ? lane : (lane - 16);
    int a_cadd = (lane < 16) ? 0 : 1;
    uint32_t aBase[2]; int aR7[2];
#pragma unroll
    for (int mt = 0; mt < 2; mt++) {
        int r = warpRow + mt * 16 + a_roff;
        aBase[mt] = smem_u + SMA + (uint32_t)r * 512;
        aR7[mt] = r & 7;
    }
    int b_noff = (lane & 7) + ((lane >= 16) ? 8 : 0);
    int b_cadd = (lane >> 3) & 1;
    uint32_t bBase[2]; int bR7[2];
#pragma unroll
    for (int p = 0; p < 2; p++) {
        int nl = warpColL + p * 16 + b_noff;
        bBase[p] = smem_u + SMB + (uint32_t)nl * 512;
        bR7[p] = nl & 7;
    }

    // ================= deterministic unit loop =================
    for (int unit = blockIdx.x; unit < nunits; unit += GRID_F) {
        int rowBase = (unit >> 1) * TILE_ROWS;

        // ---- stage A tile: 64 rows x 256 fp32 -> bf16 swizzled ----
#pragma unroll
        for (int i = 0; i < 16; i++) {
            int it = tid + i * 256;          // 0..4095 float4
            int row = it >> 6;
            int c4 = (it & 63) << 2;
            int gr = rowBase + row;
            float4 v = (gr < Npts) ? *(const float4*)(feat + (size_t)gr * DFEAT + c4)
                                   : make_float4(0.f, 0.f, 0.f, 0.f);
            __nv_bfloat162 p0 = __floats2bfloat162_rn(v.x, v.y);
            __nv_bfloat162 p1 = __floats2bfloat162_rn(v.z, v.w);
            uint32_t off = (uint32_t)row * 512
                         + (uint32_t)(((c4 >> 3) ^ (row & 7)) << 4)
                         + (uint32_t)((c4 & 4) << 1);
            *(__nv_bfloat162*)(smem + SMA + off)     = p0;
            *(__nv_bfloat162*)(smem + SMA + off + 4) = p1;
        }
        // ---- stage vdir (thread o owns slot o) ----
        if (tid < 128) {
            int b = tid >> 6, r = tid & 63;
            int gr = rowBase + r;
            bool lv = (b < B) && (gr < Npts);
            size_t gi = (size_t)b * Npts + gr;
            int o = tid;
            s_vd[o * 3 + 0] = lv ? g_vdir[gi * 3 + 0] : 0.0f;
            s_vd[o * 3 + 1] = lv ? g_vdir[gi * 3 + 1] : 0.0f;
            s_vd[o * 3 + 2] = lv ? g_vdir[gi * 3 + 2] : 0.0f;
        }
        __syncthreads();                     // A, vd, s_ra zero visible

        // ---- MMA: K=256 in 16 steps (identical to round 10 per-warp) ----
        float acc[2][4][4];
#pragma unroll
        for (int mt = 0; mt < 2; mt++)
#pragma unroll
            for (int nt = 0; nt < 4; nt++)
#pragma unroll
                for (int e = 0; e < 4; e++) acc[mt][nt][e] = 0.0f;

#pragma unroll 4
        for (int ks = 0; ks < 16; ks++) {
            int kc = ks * 2;
            uint32_t aF[2][4];
#pragma unroll
            for (int mt = 0; mt < 2; mt++)
                ldmatrix_x4(aF[mt], aBase[mt] + (uint32_t)(((kc + a_cadd) ^ aR7[mt]) << 4));
            uint32_t bF[2][4];
#pragma unroll
            for (int p = 0; p < 2; p++)
                ldmatrix_x4(bF[p], bBase[p] + (uint32_t)(((kc + b_cadd) ^ bR7[p]) << 4));
#pragma unroll
            for (int mt = 0; mt < 2; mt++)
#pragma unroll
                for (int nt = 0; nt < 4; nt++)
                    mma_bf16(acc[mt][nt], aF[mt], &bF[nt >> 1][(nt & 1) * 2]);
        }

        // ---- register epilogue, j-outer, hoisted vd ----
        float vd[MAXB][2][2][3];
#pragma unroll
        for (int b = 0; b < MAXB; b++)
#pragma unroll
            for (int mt = 0; mt < 2; mt++)
#pragma unroll
                for (int hf = 0; hf < 2; hf++) {
                    int r = warpRow + mt * 16 + g + hf * 8;
                    int o = b * 64 + r;
                    vd[b][mt][hf][0] = s_vd[o * 3 + 0];
                    vd[b][mt][hf][1] = s_vd[o * 3 + 1];
                    vd[b][mt][hf][2] = s_vd[o * 3 + 2];
                }
        float pacc[MAXB][2][2][3];
#pragma unroll
        for (int b = 0; b < MAXB; b++)
#pragma unroll
            for (int mt = 0; mt < 2; mt++)
#pragma unroll
                for (int hf = 0; hf < 2; hf++)
                    pacc[b][mt][hf][0] = pacc[b][mt][hf][1] = pacc[b][mt][hf][2] = 0.0f;

#pragma unroll
        for (int jj = 0; jj < 8; jj++) {
            int nt = jj >> 1, e1 = jj & 1;
            int j = half * 128 + warpColL + nt * 8 + tig * 2 + e1;   // global j
            float4 t1 = s_t1[j];                 // {b1, w0, w1, w2}
            float4 t2 = s_t2[j];                 // {Wa, Wb, Wc, -}
#pragma unroll
            for (int b = 0; b < MAXB; b++)
#pragma unroll
                for (int mt = 0; mt < 2; mt++)
#pragma unroll
                    for (int hf = 0; hf < 2; hf++) {
                        float h = acc[mt][nt][hf * 2 + e1] + t1.x
                                + vd[b][mt][hf][0] * t1.y
                                + vd[b][mt][hf][1] * t1.z
                                + vd[b][mt][hf][2] * t1.w;
                        h = fmaxf(h, 0.0f);
                        pacc[b][mt][hf][0] = fmaf(h, t2.x, pacc[b][mt][hf][0]);
                        pacc[b][mt][hf][1] = fmaf(h, t2.y, pacc[b][mt][hf][1]);
                        pacc[b][mt][hf][2] = fmaf(h, t2.z, pacc[b][mt][hf][2]);
                    }
        }

        // ---- quad reduce + rowacc atomics ----
#pragma unroll
        for (int b = 0; b < MAXB; b++)
#pragma unroll
            for (int mt = 0; mt < 2; mt++)
#pragma unroll
                for (int hf = 0; hf < 2; hf++) {
                    float p0 = pacc[b][mt][hf][0];
                    float p1 = pacc[b][mt][hf][1];
                    float p2 = pacc[b][mt][hf][2];
                    p0 += __shfl_xor_sync(0xFFFFFFFFu, p0, 1);
                    p0 += __shfl_xor_sync(0xFFFFFFFFu, p0, 2);
                    p1 += __shfl_xor_sync(0xFFFFFFFFu, p1, 1);
                    p1 += __shfl_xor_sync(0xFFFFFFFFu, p1, 2);
                    p2 += __shfl_xor_sync(0xFFFFFFFFu, p2, 1);
                    p2 += __shfl_xor_sync(0xFFFFFFFFu, p2, 2);
                    if (tig == 0) {
                        int r = warpRow + mt * 16 + g + hf * 8;
                        int o = b * 64 + r;
                        atomicAdd(&s_ra[o * 3 + 0], p0);
                        atomicAdd(&s_ra[o * 3 + 1], p1);
                        atomicAdd(&s_ra[o * 3 + 2], p2);
                    }
                }
        __syncthreads();                     // s_ra complete

        // ---- write partial sums (thread o owns slot o); re-zero own s_ra ----
        if (tid < 128) {
            int b = tid >> 6, r = tid & 63;
            int gr = rowBase + r;
            int o = tid;
            float r0a = s_ra[o * 3 + 0];
            float r1a = s_ra[o * 3 + 1];
            float r2a = s_ra[o * 3 + 2];
            s_ra[o * 3 + 0] = 0.0f;
            s_ra[o * 3 + 1] = 0.0f;
            s_ra[o * 3 + 2] = 0.0f;
            if (b < B && gr < Npts) {
                size_t gi = (size_t)b * Npts + gr;
                float* dst = g_pa[half] + gi * 3;
                dst[0] = r0a; dst[1] = r1a; dst[2] = r2a;
            }
        }
        // no sync: next staging writes SMA (sync-protected) and s_vd (epilogue
        // reads were before the sync above); s_ra re-zeroed by its owner thread.
    }
}

// ---------------- 5) final: sum halves, sigmoid, pixel scatter ----------------
__global__ void scatter_kernel(const float* __restrict__ b2g, int Npts, int B) {
    int i = blockIdx.x * blockDim.x + threadIdx.x;
    if (i >= B * Npts) return;
    int id = g_idx[i];
    if (id >= HW) return;
    int b = i / Npts;
    float w = g_wts[i];
    const float* pa0 = g_pa[0] + (size_t)i * 3;
    const float* pa1 = g_pa[1] + (size_t)i * 3;
    float r0 = sigmoidf_(pa0[0] + pa1[0] + b2g[0]);
    float r1 = sigmoidf_(pa0[1] + pa1[1] + b2g[1]);
    float r2 = sigmoidf_(pa0[2] + pa1[2] + b2g[2]);
    size_t base = (size_t)b * HW + id;
    atomicAdd(&g_num[base * 3 + 0], w * r0);
    atomicAdd(&g_num[base * 3 + 1], w * r1);
    atomicAdd(&g_num[base * 3 + 2], w * r2);
    atomicAdd(&g_den[base], w);
}

// ---------------- 6) composite -> output (B, 3, H, W) ----------------
__global__ void composite_kernel(const float* __restrict__ bkg,
                                 float* __restrict__ out, int B) {
    int i = blockIdx.x * blockDim.x + threadIdx.x;
    if (i >= B * HW) return;
    int b = i / HW, p = i - b * HW;
    float d = g_den[i];
    float alpha = 1.0f - expf(-d);
    float inv = __fdiv_rn(1.0f, d + 1e-8f);
#pragma unroll
    for (int c = 0; c < 3; c++) {
        float fg = g_num[(size_t)i * 3 + c] * inv;
        out[((size_t)b * 3 + c) * HW + p] = fg * alpha + bkg[c] * (1.0f - alpha);
    }
}

// ---------------- launch ----------------
extern "C" void kernel_launch(void* const* d_in, const int* in_sizes, int n_in,
                              void* d_out, int out_size) {
    const float* vert_pos = (const float*)d_in[0];
    const float* pose = (const float*)d_in[2];
    const float* intr = (const float*)d_in[3];
    const float* feat = (const float*)d_in[4];
    const float* opy  = (const float*)d_in[5];
    const float* W1   = (const float*)d_in[6];
    const float* b1   = (const float*)d_in[7];
    const float* W2   = (const float*)d_in[8];
    const float* b2   = (const float*)d_in[9];
    const float* bkg  = (const float*)d_in[10];
    float* out = (float*)d_out;

    int N = in_sizes[0] / 3;
    int B = in_sizes[2] / 16;
    if (N > MAXN) N = MAXN;
    if (B > MAXB) B = MAXB;

    cudaFuncSetAttribute(fused_gemm_kernel,
                         cudaFuncAttributeMaxDynamicSharedMemorySize, SM_TOTAL);

    prep_kernel<<<1, 32>>>(pose, B);
    init_kernel<<<(B * HW * 3 + 255) / 256, 256>>>(W1, B);
    geom_kernel<<<(B * N + 255) / 256, 256>>>(vert_pos, pose, intr, opy, N, B);

    int nunits = ((N + TILE_ROWS - 1) / TILE_ROWS) * 2;   // (rowtile, half)
    fused_gemm_kernel<<<GRID_F, 256, SM_TOTAL>>>(feat, W1, b1, W2, N, B, nunits);

    scatter_kernel<<<(B * N + 255) / 256, 256>>>(b2, N, B);
    composite_kernel<<<(B * HW + 255) / 256, 256>>>(bkg, out, B);
}

// round 12
// speedup vs baseline: 1.1504x; 1.1504x over previous
#include <cuda_runtime.h>
#include <cuda_bf16.h>
#include <math.h>
#include <cstdint>

#define MAXN 200000
#define MAXB 2
#define IMG_H 300
#define IMG_W 400
#define HW (IMG_H * IMG_W)
#define DFEAT 256
#define HID 256

// ---------------- scratch (static device globals; no allocation) ----------------
__device__ float g_vdir[(size_t)MAXB * MAXN * 3];
__device__ float g_wts[(size_t)MAXB * MAXN];
__device__ int   g_idx[(size_t)MAXB * MAXN];
__device__ float g_num[(size_t)MAXB * HW * 3];
__device__ float g_den[(size_t)MAXB * HW];
__device__ float g_pinv[MAXB * 16];
__device__ __nv_bfloat16 g_W1T[DFEAT * HID];   // W1T[n][k] = W1[k][n], bf16, K-major

__device__ __forceinline__ float sigmoidf_(float x) {
    return 1.0f / (1.0f + expf(-x));
}

// No-FMA dot product — matches XLA fusion codegen. DO NOT TOUCH.
__device__ __forceinline__ float dot3_nofma(float a0, float a1, float a2,
                                            float x0, float x1, float x2) {
    float t0 = __fmul_rn(a0, x0);
    float t1 = __fmul_rn(a1, x1);
    float t2 = __fmul_rn(a2, x2);
    return __fadd_rn(__fadd_rn(t0, t1), t2);
}

__device__ __forceinline__ uint32_t smem_to_u32(const void* p) {
    uint32_t a;
    asm("{ .reg .u64 t; cvta.to.shared.u64 t, %1; cvt.u32.u64 %0, t; }" : "=r"(a) : "l"(p));
    return a;
}

// ---------------- 1) 4x4 pose inverse ----------------
__global__ void prep_kernel(const float* __restrict__ pose, int B) {
    int b = threadIdx.x;
    if (b >= B) return;
    float a[4][8];
    for (int r = 0; r < 4; r++)
        for (int c = 0; c < 4; c++) {
            a[r][c] = pose[b * 16 + r * 4 + c];
            a[r][4 + c] = (r == c) ? 1.0f : 0.0f;
        }
    for (int col = 0; col < 4; col++) {
        int piv = col;
        for (int r = col + 1; r < 4; r++)
            if (fabsf(a[r][col]) > fabsf(a[piv][col])) piv = r;
        if (piv != col)
            for (int c = 0; c < 8; c++) { float t = a[col][c]; a[col][c] = a[piv][c]; a[piv][c] = t; }
        float d = 1.0f / a[col][col];
        for (int c = 0; c < 8; c++) a[col][c] *= d;
        for (int r = 0; r < 4; r++) {
            if (r == col) continue;
            float f = a[r][col];
            for (int c = 0; c < 8; c++) a[r][c] -= f * a[col][c];
        }
    }
    for (int r = 0; r < 4; r++)
        for (int c = 0; c < 4; c++)
            g_pinv[b * 16 + r * 4 + c] = a[r][4 + c];
}

// ------- 2) init: zero accumulators + convert W1[0:256] -> bf16 K-major -------
__global__ void init_kernel(const float* __restrict__ W1, int B) {
    int i = blockIdx.x * blockDim.x + threadIdx.x;
    if (i < DFEAT * HID) {
        int k = i >> 8, n = i & 255;            // read coalesced over n
        g_W1T[n * DFEAT + k] = __float2bfloat16(W1[k * HID + n]);
    }
    int n3 = B * HW * 3;
    if (i < n3) g_num[i] = 0.0f;
    if (i < B * HW) g_den[i] = 0.0f;
}

// ---------------- 3) geometry (exact arithmetic — passes at 9e-8) ----------------
__global__ void geom_kernel(const float* __restrict__ vert_pos,
                            const float* __restrict__ pose,
                            const float* __restrict__ intr,
                            const float* __restrict__ opy,
                            int N, int B) {
    int i = blockIdx.x * blockDim.x + threadIdx.x;
    if (i >= B * N) return;
    int b = i / N, n = i - b * N;

    float px = vert_pos[n], py = vert_pos[N + n], pz = vert_pos[2 * N + n];
    const float* P = pose + b * 16;
    float x = __fadd_rn(dot3_nofma(P[0], P[1], P[2],  px, py, pz), __fmul_rn(P[3],  1.0f));
    float y = __fadd_rn(dot3_nofma(P[4], P[5], P[6],  px, py, pz), __fmul_rn(P[7],  1.0f));
    float z = __fadd_rn(dot3_nofma(P[8], P[9], P[10], px, py, pz), __fmul_rn(P[11], 1.0f));

    const float* Km = intr + b * 9;
    float u_ = dot3_nofma(Km[0], Km[1], Km[2], x, y, z);
    float v_ = dot3_nofma(Km[3], Km[4], Km[5], x, y, z);
    float w_ = dot3_nofma(Km[6], Km[7], Km[8], x, y, z);

    bool em = fabsf(w_) < 0.01f;
    float zs = em ? 0.01f : w_;
    float su = em ? -1e6f : __fdiv_rn(u_, zs);
    float sv = em ? -1e6f : __fdiv_rn(v_, zs);
    float sz = em ? -1e6f : zs;

    float inorm = rsqrtf(x * x + y * y + z * z);
    float nx = x * inorm, ny = y * inorm, nz = z * inorm;
    const float* Pi = g_pinv + b * 16;
    g_vdir[(size_t)i * 3 + 0] = dot3_nofma(Pi[0], Pi[1], Pi[2],  nx, ny, nz);
    g_vdir[(size_t)i * 3 + 1] = dot3_nofma(Pi[4], Pi[5], Pi[6],  nx, ny, nz);
    g_vdir[(size_t)i * 3 + 2] = dot3_nofma(Pi[8], Pi[9], Pi[10], nx, ny, nz);

    int ix = (int)rintf(su);
    int iy = (int)rintf(sv);
    bool valid = (ix >= 0) && (ix < IMG_W) && (iy >= 0) && (iy < IMG_H) && (sz >= 1.0f);
    g_idx[i] = valid ? iy * IMG_W + ix : HW;
    float op = sigmoidf_(opy[n]);
    op = fminf(fmaxf(op, 0.0f), 1.0f);
    g_wts[i] = valid ? op : 0.0f;
}

// ============ 4) persistent fused HMMA GEMM + tensor-core W2 epilogue =========
// Round-10 structure (152 CTAs x 512 thr, 2 syncs/tile, scatter overlapped),
// but the epilogue's h@W2 projection now runs on the TENSOR pipe:
// acc fragments (after b1+vdir+relu, packed to bf16) feed mma directly as the
// A operand (m16n8 C-layout pair == m16k16 A-layout), against constant W2
// B-fragments. No pacc, no shuffles; channels land whole in lanes tig=0/1.
#define TILE_ROWS 64
// SMEM byte offsets
#define SMB   0                      // B tile: 256 n-rows x 512B          = 131072
#define SMA   131072                 // A tile: 64 rows x 512B             = 32768
#define SMT1  163840                 // t1[256] float4 {b1,w0,w1,w2}       = 4096
#define SMVD  172032                 // vdir  [2][64][3] floats            = 1536
#define SMW   173568                 // wts   [2][64]                      = 512
#define SMID  174080                 // idx   [2][64] int                  = 512
#define SMRA  174592                 // rowacc[2][64][3] floats            = 1536
#define SM_TOTAL 176128

__device__ __forceinline__ void ldmatrix_x4(uint32_t* r, uint32_t addr) {
    asm volatile("ldmatrix.sync.aligned.m8n8.x4.shared.b16 {%0,%1,%2,%3}, [%4];"
                 : "=r"(r[0]), "=r"(r[1]), "=r"(r[2]), "=r"(r[3]) : "r"(addr));
}
__device__ __forceinline__ void mma_bf16(float* d, const uint32_t* a, const uint32_t* b) {
    asm volatile(
        "mma.sync.aligned.m16n8k16.row.col.f32.bf16.bf16.f32 "
        "{%0,%1,%2,%3}, {%4,%5,%6,%7}, {%8,%9}, {%0,%1,%2,%3};"
        : "+f"(d[0]), "+f"(d[1]), "+f"(d[2]), "+f"(d[3])
        : "r"(a[0]), "r"(a[1]), "r"(a[2]), "r"(a[3]), "r"(b[0]), "r"(b[1]));
}
__device__ __forceinline__ uint32_t packbf2(float lo, float hi) {
    __nv_bfloat162 p = __floats2bfloat162_rn(lo, hi);
    return *(uint32_t*)&p;
}

__global__ __launch_bounds__(512, 1) void fused_gemm_kernel(
    const float* __restrict__ feat,
    const float* __restrict__ W1,
    const float* __restrict__ b1g,
    const float* __restrict__ W2g,
    const float* __restrict__ b2g,
    int Npts, int B, int ntiles)
{
    extern __shared__ char smem[];
    uint32_t smem_u = smem_to_u32(smem);
    int tid = threadIdx.x;
    int wid = tid >> 5;
    int lane = tid & 31;
    int g = lane >> 2;                 // row group within mma fragment
    int tig = lane & 3;                // col pair within mma fragment

    float4* s_t1 = (float4*)(smem + SMT1);
    float* s_vd  = (float*)(smem + SMVD);    // [(b*64+r)*3 + c]
    float* s_wt  = (float*)(smem + SMW);     // [b*64+r]
    int*   s_id  = (int*)  (smem + SMID);    // [b*64+r]
    float* s_ra  = (float*)(smem + SMRA);    // [(b*64+r)*3 + c]

    // ---- load B tile ONCE: g_W1T 256(n) x 256(k) bf16, swizzled ----
    for (int it = tid; it < 8192; it += 512) {
        int n = it >> 5;
        int chunk = it & 31;
        uint4 v = *(const uint4*)(g_W1T + (size_t)n * DFEAT + (chunk << 3));
        uint32_t off = (uint32_t)n * 512 + (uint32_t)((chunk ^ (n & 7)) << 4);
        *(uint4*)(smem + SMB + off) = v;
    }
    // ---- t1 table {b1, w1row256, w1row257, w1row258} ----
    if (tid < 256) {
        s_t1[tid] = make_float4(b1g[tid],
                                W1[(size_t)DFEAT * HID + tid],
                                W1[(size_t)(DFEAT + 1) * HID + tid],
                                W1[(size_t)(DFEAT + 2) * HID + tid]);
    }
    if (tid < 384) s_ra[tid] = 0.0f;         // zero ALL 384 rowacc floats
    float bb0 = b2g[0], bb1 = b2g[1], bb2 = b2g[2];

    // ---- warp tiling / ldmatrix addressing (validated rounds 6-10) ----
    int warpRow = (wid >> 3) * 32;     // 0 or 32
    int warpCol = (wid & 7) * 32;      // 0..224
    int a_roff = (lane < 16) ? lane : (lane - 16);
    int a_cadd = (lane < 16) ? 0 : 1;
    uint32_t aBase[2]; int aR7[2];
#pragma unroll
    for (int mt = 0; mt < 2; mt++) {
        int r = warpRow + mt * 16 + a_roff;
        aBase[mt] = smem_u + SMA + (uint32_t)r * 512;
        aR7[mt] = r & 7;
    }
    int b_noff = (lane & 7) + ((lane >= 16) ? 8 : 0);
    int b_cadd = (lane >> 3) & 1;
    uint32_t bBase[2]; int bR7[2];
#pragma unroll
    for (int p = 0; p < 2; p++) {
        int n = warpCol + p * 16 + b_noff;
        bBase[p] = smem_u + SMB + (uint32_t)n * 512;
        bR7[p] = n & 7;
    }

    // ---- constant W2 B-fragments (m16n8k16 B layout: k=2*tig+(i&1)+8*reg, n=g) ----
    // Second GEMM: k = local hidden j (2 chunks of 16 per warp), n = channel (0..2).
    uint32_t w2f[2][2];
#pragma unroll
    for (int c = 0; c < 2; c++) {
#pragma unroll
        for (int rr = 0; rr < 2; rr++) {
            int j0 = warpCol + 16 * c + 2 * tig + 8 * rr;
            float lo = (g < 3) ? W2g[j0 * 3 + g] : 0.0f;
            float hi = (g < 3) ? W2g[(j0 + 1) * 3 + g] : 0.0f;
            w2f[c][rr] = packbf2(lo, hi);
        }
    }

    // ================= deterministic tile loop =================
    for (int tile = blockIdx.x; tile < ntiles; tile += gridDim.x) {
        int rowBase = tile * TILE_ROWS;

        // ---- stage A tile: 64 rows x 256 fp32 -> bf16 swizzled (8B STS) ----
#pragma unroll
        for (int i = 0; i < 8; i++) {
            int it = tid + i * 512;          // 0..4095 float4
            int row = it >> 6;
            int c4 = (it & 63) << 2;
            int gr = rowBase + row;
            float4 v = (gr < Npts) ? *(const float4*)(feat + (size_t)gr * DFEAT + c4)
                                   : make_float4(0.f, 0.f, 0.f, 0.f);
            uint2 pk = make_uint2(packbf2(v.x, v.y), packbf2(v.z, v.w));
            uint32_t off = (uint32_t)row * 512
                         + (uint32_t)(((c4 >> 3) ^ (row & 7)) << 4)
                         + (uint32_t)((c4 & 4) << 1);
            *(uint2*)(smem + SMA + off) = pk;
        }
        // ---- stage per-point data (thread o owns slot o) ----
        if (tid < 128) {
            int b = tid >> 6, r = tid & 63;
            int gr = rowBase + r;
            bool lv = (b < B) && (gr < Npts);
            size_t gi = (size_t)b * Npts + gr;
            int o = tid;
            s_vd[o * 3 + 0] = lv ? g_vdir[gi * 3 + 0] : 0.0f;
            s_vd[o * 3 + 1] = lv ? g_vdir[gi * 3 + 1] : 0.0f;
            s_vd[o * 3 + 2] = lv ? g_vdir[gi * 3 + 2] : 0.0f;
            s_wt[o] = lv ? g_wts[gi] : 0.0f;
            s_id[o] = lv ? g_idx[gi] : HW;
        }
        __syncthreads();                     // A, pts, s_ra zero visible

        // ---- MMA: K=256 in 16 steps ----
        float acc[2][4][4];
#pragma unroll
        for (int mt = 0; mt < 2; mt++)
#pragma unroll
            for (int nt = 0; nt < 4; nt++)
#pragma unroll
                for (int e = 0; e < 4; e++) acc[mt][nt][e] = 0.0f;

#pragma unroll 4
        for (int ks = 0; ks < 16; ks++) {
            int kc = ks * 2;
            uint32_t aF[2][4];
#pragma unroll
            for (int mt = 0; mt < 2; mt++)
                ldmatrix_x4(aF[mt], aBase[mt] + (uint32_t)(((kc + a_cadd) ^ aR7[mt]) << 4));
            uint32_t bF[2][4];
#pragma unroll
            for (int p = 0; p < 2; p++)
                ldmatrix_x4(bF[p], bBase[p] + (uint32_t)(((kc + b_cadd) ^ bR7[p]) << 4));
#pragma unroll
            for (int mt = 0; mt < 2; mt++)
#pragma unroll
                for (int nt = 0; nt < 4; nt++)
                    mma_bf16(acc[mt][nt], aF[mt], &bF[nt >> 1][(nt & 1) * 2]);
        }

        // ---- epilogue: b1+vdir+relu elementwise, then h@W2 on the tensor pipe ----
        float vd[MAXB][2][2][3];             // [b][mt][hf(row g / g+8)][c]
#pragma unroll
        for (int b = 0; b < MAXB; b++)
#pragma unroll
            for (int mt = 0; mt < 2; mt++)
#pragma unroll
                for (int hf = 0; hf < 2; hf++) {
                    int r = warpRow + mt * 16 + g + hf * 8;
                    int o = b * 64 + r;
                    vd[b][mt][hf][0] = s_vd[o * 3 + 0];
                    vd[b][mt][hf][1] = s_vd[o * 3 + 1];
                    vd[b][mt][hf][2] = s_vd[o * 3 + 2];
                }
        float d4[MAXB][2][4];                // second-gemm acc: [b][mt][e]
#pragma unroll
        for (int b = 0; b < MAXB; b++)
#pragma unroll
            for (int mt = 0; mt < 2; mt++)
#pragma unroll
                for (int e = 0; e < 4; e++) d4[b][mt][e] = 0.0f;

#pragma unroll
        for (int c = 0; c < 2; c++) {
            // t1 for the 4 distinct j's this thread touches in chunk c
            float4 T0 = s_t1[warpCol + 16 * c + 2 * tig];       // nt=2c,   e1=0
            float4 T1 = s_t1[warpCol + 16 * c + 2 * tig + 1];   // nt=2c,   e1=1
            float4 T2 = s_t1[warpCol + 16 * c + 2 * tig + 8];   // nt=2c+1, e1=0
            float4 T3 = s_t1[warpCol + 16 * c + 2 * tig + 9];   // nt=2c+1, e1=1
            int nl = 2 * c, nh = 2 * c + 1;
#pragma unroll
            for (int b = 0; b < MAXB; b++)
#pragma unroll
                for (int mt = 0; mt < 2; mt++) {
                    float* v0 = vd[b][mt][0];   // row g
                    float* v1 = vd[b][mt][1];   // row g+8
                    float h0 = fmaxf(acc[mt][nl][0] + T0.x + v0[0]*T0.y + v0[1]*T0.z + v0[2]*T0.w, 0.f);
                    float h1 = fmaxf(acc[mt][nl][1] + T1.x + v0[0]*T1.y + v0[1]*T1.z + v0[2]*T1.w, 0.f);
                    float h2 = fmaxf(acc[mt][nl][2] + T0.x + v1[0]*T0.y + v1[1]*T0.z + v1[2]*T0.w, 0.f);
                    float h3 = fmaxf(acc[mt][nl][3] + T1.x + v1[0]*T1.y + v1[1]*T1.z + v1[2]*T1.w, 0.f);
                    float h4 = fmaxf(acc[mt][nh][0] + T2.x + v0[0]*T2.y + v0[1]*T2.z + v0[2]*T2.w, 0.f);
                    float h5 = fmaxf(acc[mt][nh][1] + T3.x + v0[0]*T3.y + v0[1]*T3.z + v0[2]*T3.w, 0.f);
                    float h6 = fmaxf(acc[mt][nh][2] + T2.x + v1[0]*T2.y + v1[1]*T2.z + v1[2]*T2.w, 0.f);
                    float h7 = fmaxf(acc[mt][nh][3] + T3.x + v1[0]*T3.y + v1[1]*T3.z + v1[2]*T3.w, 0.f);
                    // acc(C m16n8) pair -> A(m16k16) fragment (FA P.V identity)
                    uint32_t af[4];
                    af[0] = packbf2(h0, h1);     // (row g,   k 2tig..)
                    af[1] = packbf2(h2, h3);     // (row g+8, k 2tig..)
                    af[2] = packbf2(h4, h5);     // (row g,   k 2tig+8..)
                    af[3] = packbf2(h6, h7);     // (row g+8, k 2tig+8..)
                    mma_bf16(d4[b][mt], af, w2f[c]);
                }
        }

        // ---- cross-warp reduce via s_ra (channels whole per lane: n=2tig+e1) ----
#pragma unroll
        for (int b = 0; b < MAXB; b++)
#pragma unroll
            for (int mt = 0; mt < 2; mt++) {
                int r0 = warpRow + mt * 16 + g;
                int o0 = b * 64 + r0, o1 = o0 + 8;
                if (tig == 0) {
                    atomicAdd(&s_ra[o0 * 3 + 0], d4[b][mt][0]);  // n=0 -> ch0
                    atomicAdd(&s_ra[o0 * 3 + 1], d4[b][mt][1]);  // n=1 -> ch1
                    atomicAdd(&s_ra[o1 * 3 + 0], d4[b][mt][2]);
                    atomicAdd(&s_ra[o1 * 3 + 1], d4[b][mt][3]);
                } else if (tig == 1) {
                    atomicAdd(&s_ra[o0 * 3 + 2], d4[b][mt][0]);  // n=2 -> ch2
                    atomicAdd(&s_ra[o1 * 3 + 2], d4[b][mt][2]);
                }
            }
        __syncthreads();                     // s_ra complete

        // ---- scatter (thread o owns slot o); zero own s_ra for next tile ----
        if (tid < 128) {
            int b = tid >> 6;
            int o = tid;
            int id = s_id[o];
            float r0a = s_ra[o * 3 + 0];
            float r1a = s_ra[o * 3 + 1];
            float r2a = s_ra[o * 3 + 2];
            s_ra[o * 3 + 0] = 0.0f;
            s_ra[o * 3 + 1] = 0.0f;
            s_ra[o * 3 + 2] = 0.0f;
            if (id < HW) {
                float w = s_wt[o];
                float r0 = sigmoidf_(r0a + bb0);
                float r1 = sigmoidf_(r1a + bb1);
                float r2 = sigmoidf_(r2a + bb2);
                size_t base = (size_t)b * HW + id;
                atomicAdd(&g_num[base * 3 + 0], w * r0);
                atomicAdd(&g_num[base * 3 + 1], w * r1);
                atomicAdd(&g_num[base * 3 + 2], w * r2);
                atomicAdd(&g_den[base], w);
            }
        }
        // no sync: next staging writes SMA (sync-protected) and per-point slots
        // owned by the same thread that just read them.
    }
}

// ---------------- 6) composite -> output (B, 3, H, W) ----------------
__global__ void composite_kernel(const float* __restrict__ bkg,
                                 float* __restrict__ out, int B) {
    int i = blockIdx.x * blockDim.x + threadIdx.x;
    if (i >= B * HW) return;
    int b = i / HW, p = i - b * HW;
    float d = g_den[i];
    float alpha = 1.0f - expf(-d);
    float inv = __fdiv_rn(1.0f, d + 1e-8f);
#pragma unroll
    for (int c = 0; c < 3; c++) {
        float fg = g_num[(size_t)i * 3 + c] * inv;
        out[((size_t)b * 3 + c) * HW + p] = fg * alpha + bkg[c] * (1.0f - alpha);
    }
}

// ---------------- launch ----------------
extern "C" void kernel_launch(void* const* d_in, const int* in_sizes, int n_in,
                              void* d_out, int out_size) {
    const float* vert_pos = (const float*)d_in[0];
    const float* pose = (const float*)d_in[2];
    const float* intr = (const float*)d_in[3];
    const float* feat = (const float*)d_in[4];
    const float* opy  = (const float*)d_in[5];
    const float* W1   = (const float*)d_in[6];
    const float* b1   = (const float*)d_in[7];
    const float* W2   = (const float*)d_in[8];
    const float* b2   = (const float*)d_in[9];
    const float* bkg  = (const float*)d_in[10];
    float* out = (float*)d_out;

    int N = in_sizes[0] / 3;
    int B = in_sizes[2] / 16;
    if (N > MAXN) N = MAXN;
    if (B > MAXB) B = MAXB;

    cudaFuncSetAttribute(fused_gemm_kernel,
                         cudaFuncAttributeMaxDynamicSharedMemorySize, SM_TOTAL);

    prep_kernel<<<1, 32>>>(pose, B);
    init_kernel<<<(B * HW * 3 + 255) / 256, 256>>>(W1, B);
    geom_kernel<<<(B * N + 255) / 256, 256>>>(vert_pos, pose, intr, opy, N, B);

    int ntiles = (N + TILE_ROWS - 1) / TILE_ROWS;
    fused_gemm_kernel<<<152, 512, SM_TOTAL>>>(feat, W1, b1, W2, b2, N, B, ntiles);

    composite_kernel<<<(B * HW + 255) / 256, 256>>>(bkg, out, B);
}